// round 9
// baseline (speedup 1.0000x reference)
#include <cuda_runtime.h>

// Problem constants (fixed shapes from setup_inputs)
#define NB      64
#define T_LEN   2048
#define DDIM    80
#define N_ELEM  (NB * T_LEN * DDIM)   // 10,485,760
#define N_VEC   (N_ELEM / 4)          // 2,621,440 float4 elements
#define VPR     (DDIM / 4)            // 20 float4 per row

#define GBLOCKS 1184                  // 8 CTAs per SM on 148 SMs
#define GTHREADS 256

// Scratch (no device allocation allowed)
__device__ float        g_pc[GBLOCKS];
__device__ float        g_pl[GBLOCKS];
__device__ unsigned int g_count = 0;

__device__ __forceinline__ float ex2f(float x) {
    float y; asm("ex2.approx.f32 %0, %1;" : "=f"(y) : "f"(x)); return y;
}
__device__ __forceinline__ float lg2f(float x) {
    float y; asm("lg2.approx.f32 %0, %1;" : "=f"(y) : "f"(x)); return y;
}

__global__ void __launch_bounds__(GTHREADS)
jitter_fused(const float* __restrict__ in, const float* __restrict__ tg,
             float* __restrict__ out)
{
    // ex2 argument scale: -k * log2(e), k = 32
    const float C  = -32.0f * 1.4426950408889634f;

    float accC = 0.0f;   // sum of center abs-diffs
    float accL = 0.0f;   // sum of lg2(softmin-sum)

    for (unsigned g = blockIdx.x * GTHREADS + threadIdx.x; g < N_VEC;
         g += GBLOCKS * GTHREADS)
    {
        unsigned row = g / VPR;          // flattened (b, i) row in [0, 64*2048)
        unsigned jj  = g - row * VPR;    // float4 slot within the row, [0, 20)
        unsigned i   = row & (T_LEN - 1);

        const float* ip = in + (size_t)row * DDIM + jj * 4;
        const float* tp = tg + (size_t)row * DDIM + jj * 4;

        float4 x4 = *reinterpret_cast<const float4*>(ip);
        float x[4] = {x4.x, x4.y, x4.z, x4.w};

        // 3 target rows (i-1, i, i+1) x 6 cols (j-1 .. j+4), zero-padded OOB
        float t[3][6];
        const bool upv = (i > 0);
        const bool dnv = (i < T_LEN - 1);
        const bool lv  = (jj > 0);
        const bool rv  = (jj < VPR - 1);

        const float* rows[3] = {tp - DDIM, tp, tp + DDIM};
        const bool   rok[3]  = {upv, true, dnv};

        #pragma unroll
        for (int r = 0; r < 3; r++) {
            if (rok[r]) {
                float4 t4 = *reinterpret_cast<const float4*>(rows[r]);
                t[r][1] = t4.x; t[r][2] = t4.y; t[r][3] = t4.z; t[r][4] = t4.w;
                t[r][0] = lv ? rows[r][-1] : 0.0f;
                t[r][5] = rv ? rows[r][4]  : 0.0f;
            } else {
                #pragma unroll
                for (int c = 0; c < 6; c++) t[r][c] = 0.0f;
            }
        }

        #pragma unroll
        for (int e = 0; e < 4; e++) {
            float xv = x[e];
            float s = 0.0f;
            #pragma unroll
            for (int r = 0; r < 3; r++) {
                #pragma unroll
                for (int c = 0; c < 3; c++) {
                    float d = fabsf(xv - t[r][e + c]);
                    s += ex2f(C * d);
                }
            }
            float center = fabsf(xv - t[1][e + 1]);   // (dy=0, dx=0)
            accC += center;
            accL += lg2f(fmaxf(s, 1e-37f));
        }
    }

    // ---- deterministic block tree reduction (as in R1) ----
    __shared__ float shc[GTHREADS];
    __shared__ float shl[GTHREADS];
    shc[threadIdx.x] = accC;
    shl[threadIdx.x] = accL;
    __syncthreads();
    #pragma unroll
    for (int off = GTHREADS / 2; off > 0; off >>= 1) {
        if (threadIdx.x < off) {
            shc[threadIdx.x] += shc[threadIdx.x + off];
            shl[threadIdx.x] += shl[threadIdx.x + off];
        }
        __syncthreads();
    }

    // ---- fused final reduction via ticket (last block) ----
    __shared__ bool isLast;
    if (threadIdx.x == 0) {
        g_pc[blockIdx.x] = shc[0];
        g_pl[blockIdx.x] = shl[0];
        __threadfence();
        unsigned ticket = atomicAdd(&g_count, 1u);
        isLast = (ticket == GBLOCKS - 1);
    }
    __syncthreads();

    if (isLast) {
        __shared__ double dsc[GTHREADS];
        __shared__ double dsl[GTHREADS];
        double dc = 0.0, dl = 0.0;
        for (int k = threadIdx.x; k < GBLOCKS; k += GTHREADS) {
            dc += (double)__ldcg(&g_pc[k]);
            dl += (double)__ldcg(&g_pl[k]);
        }
        dsc[threadIdx.x] = dc;
        dsl[threadIdx.x] = dl;
        __syncthreads();
        #pragma unroll
        for (int off = GTHREADS / 2; off > 0; off >>= 1) {
            if (threadIdx.x < off) {
                dsc[threadIdx.x] += dsc[threadIdx.x + off];
                dsl[threadIdx.x] += dsl[threadIdx.x + off];
            }
            __syncthreads();
        }
        if (threadIdx.x == 0) {
            const double C2d = -0.021660849392498291;  // -ln(2)/32
            double res = (0.5 / (double)N_ELEM) * (dsc[0] + C2d * dsl[0]);
            out[0] = (float)res;
            g_count = 0;   // reset ticket for graph replay
        }
    }
}

extern "C" void kernel_launch(void* const* d_in, const int* in_sizes, int n_in,
                              void* d_out, int out_size)
{
    const float* in = (const float*)d_in[0];
    const float* tg = (const float*)d_in[1];
    float* out = (float*)d_out;

    jitter_fused<<<GBLOCKS, GTHREADS>>>(in, tg, out);
}

// round 10
// speedup vs baseline: 1.0643x; 1.0643x over previous
#include <cuda_runtime.h>

// Problem constants (fixed shapes from setup_inputs)
#define NB      64
#define T_LEN   2048
#define DDIM    80
#define N_ROWS  (NB * T_LEN)          // 131072
#define N_ELEM  (N_ROWS * DDIM)       // 10,485,760
#define N_VEC   (N_ELEM / 4)          // 2,621,440 float4 elements
#define VPR     (DDIM / 4)            // 20 float4 per row

#define GTHREADS 256
#define GBLOCKS  1180                 // ~8 CTAs/SM AND stride % 20 == 0
#define STRIDE   (GBLOCKS * GTHREADS) // 302080 = 20 * 15104
#define ROWSTEP  (STRIDE / VPR)       // 15104 rows per loop step

// Scratch (no device allocation allowed)
__device__ float        g_pc[GBLOCKS];
__device__ float        g_pl[GBLOCKS];
__device__ unsigned int g_count = 0;

__device__ __forceinline__ float ex2f(float x) {
    float y; asm("ex2.approx.f32 %0, %1;" : "=f"(y) : "f"(x)); return y;
}
__device__ __forceinline__ float lg2f(float x) {
    float y; asm("lg2.approx.f32 %0, %1;" : "=f"(y) : "f"(x)); return y;
}

__global__ void __launch_bounds__(GTHREADS)
jitter_fused(const float* __restrict__ in, const float* __restrict__ tg,
             float* __restrict__ out)
{
    // ex2 argument scale: -k * log2(e), k = 32
    const float C = -32.0f * 1.4426950408889634f;

    const unsigned t = blockIdx.x * GTHREADS + threadIdx.x;

    // Loop-invariant (STRIDE is a multiple of VPR): computed exactly once.
    const unsigned jj = t % VPR;          // float4 slot within row
    const unsigned r0 = t / VPR;          // starting row
    const int  base = jj * 4;
    const bool lv   = (jj > 0);
    const bool rv   = (jj < VPR - 1);

    float accC = 0.0f;   // sum of center abs-diffs
    float accL = 0.0f;   // sum of lg2(softmin-sum)

    #pragma unroll 1
    for (unsigned row = r0; row < N_ROWS; row += ROWSTEP) {
        const unsigned i = row & (T_LEN - 1);

        const float* ip = in + (size_t)row * DDIM + base;
        const float* tp = tg + (size_t)row * DDIM + base;

        float4 x4 = *reinterpret_cast<const float4*>(ip);
        float x[4] = {x4.x, x4.y, x4.z, x4.w};

        // 3 target rows (i-1, i, i+1) x 6 cols (j-1 .. j+4), zero-padded OOB
        float tv[3][6];
        const float* rows[3] = {tp - DDIM, tp, tp + DDIM};
        const bool   rok[3]  = {i > 0, true, i < T_LEN - 1};

        #pragma unroll
        for (int r = 0; r < 3; r++) {
            if (rok[r]) {
                float4 t4 = *reinterpret_cast<const float4*>(rows[r]);
                tv[r][1] = t4.x; tv[r][2] = t4.y; tv[r][3] = t4.z; tv[r][4] = t4.w;
                tv[r][0] = lv ? rows[r][-1] : 0.0f;
                tv[r][5] = rv ? rows[r][4]  : 0.0f;
            } else {
                #pragma unroll
                for (int c = 0; c < 6; c++) tv[r][c] = 0.0f;
            }
        }

        #pragma unroll
        for (int e = 0; e < 4; e++) {
            float xv = x[e];
            float s = 1e-37f;            // underflow guard folded into the seed
            #pragma unroll
            for (int r = 0; r < 3; r++) {
                #pragma unroll
                for (int c = 0; c < 3; c++) {
                    float d = fabsf(xv - tv[r][e + c]);
                    s += ex2f(C * d);
                }
            }
            accC += fabsf(xv - tv[1][e + 1]);   // center (dy=0, dx=0)
            accL += lg2f(s);
        }
    }

    // ---- deterministic block tree reduction ----
    __shared__ float shc[GTHREADS];
    __shared__ float shl[GTHREADS];
    shc[threadIdx.x] = accC;
    shl[threadIdx.x] = accL;
    __syncthreads();
    #pragma unroll
    for (int off = GTHREADS / 2; off > 0; off >>= 1) {
        if (threadIdx.x < off) {
            shc[threadIdx.x] += shc[threadIdx.x + off];
            shl[threadIdx.x] += shl[threadIdx.x + off];
        }
        __syncthreads();
    }

    // ---- fused final reduction via ticket (last block) ----
    __shared__ bool isLast;
    if (threadIdx.x == 0) {
        g_pc[blockIdx.x] = shc[0];
        g_pl[blockIdx.x] = shl[0];
        __threadfence();
        unsigned ticket = atomicAdd(&g_count, 1u);
        isLast = (ticket == GBLOCKS - 1);
    }
    __syncthreads();

    if (isLast) {
        __shared__ double dsc[GTHREADS];
        __shared__ double dsl[GTHREADS];
        double dc = 0.0, dl = 0.0;
        for (int k = threadIdx.x; k < GBLOCKS; k += GTHREADS) {
            dc += (double)__ldcg(&g_pc[k]);
            dl += (double)__ldcg(&g_pl[k]);
        }
        dsc[threadIdx.x] = dc;
        dsl[threadIdx.x] = dl;
        __syncthreads();
        #pragma unroll
        for (int off = GTHREADS / 2; off > 0; off >>= 1) {
            if (threadIdx.x < off) {
                dsc[threadIdx.x] += dsc[threadIdx.x + off];
                dsl[threadIdx.x] += dsl[threadIdx.x + off];
            }
            __syncthreads();
        }
        if (threadIdx.x == 0) {
            const double C2d = -0.021660849392498291;  // -ln(2)/32
            double res = (0.5 / (double)N_ELEM) * (dsc[0] + C2d * dsl[0]);
            out[0] = (float)res;
            g_count = 0;   // reset ticket for graph replay
        }
    }
}

extern "C" void kernel_launch(void* const* d_in, const int* in_sizes, int n_in,
                              void* d_out, int out_size)
{
    const float* in = (const float*)d_in[0];
    const float* tg = (const float*)d_in[1];
    float* out = (float*)d_out;

    jitter_fused<<<GBLOCKS, GTHREADS>>>(in, tg, out);
}